// round 1
// baseline (speedup 1.0000x reference)
#include <cuda_runtime.h>

// Problem constants (B, L, D, H fixed by the dataset)
#define NB 4
#define NL 1024
#define ND 512
#define NH 8
#define NHD 64
#define NM (NB * NL)      // 4096 rows
#define NQKV (3 * ND)     // 1536

#define NEGV (-1.0e9f)

// Scratch (allocation-free rule: __device__ globals)
__device__ float g_qkv[(size_t)NM * NQKV];   // 4096 x 1536
__device__ float g_attn[(size_t)NM * ND];    // 4096 x 512

// ---------------------------------------------------------------------------
// TN SGEMM: C[m][n] = sum_k A[m][k] * B[n][k] (+ bias[n])
// A: MxK row-major, B: NxK row-major. Block 128x128, K-tile 16, 8x8/thread.
// Requires M%128==0, N%128==0, K%16==0 (true for all three GEMMs here).
// ---------------------------------------------------------------------------
__global__ __launch_bounds__(256) void sgemm_tn_kernel(
    const float* __restrict__ A, const float* __restrict__ Bw,
    const float* __restrict__ bias, float* __restrict__ C,
    int M, int N, int K)
{
    __shared__ float As[16][128];
    __shared__ float Bs[16][128];

    const int tid = threadIdx.x;
    const int tx = tid & 15;        // column group
    const int ty = tid >> 4;        // row group

    const float* Ab = A + (size_t)blockIdx.y * 128 * K;
    const float* Bb = Bw + (size_t)blockIdx.x * 128 * K;

    float acc[8][8];
#pragma unroll
    for (int i = 0; i < 8; i++)
#pragma unroll
        for (int j = 0; j < 8; j++) acc[i][j] = 0.0f;

    for (int k0 = 0; k0 < K; k0 += 16) {
        // Load 128x16 tiles of A and B (2048 floats each = 2 float4/thread)
#pragma unroll
        for (int l = 0; l < 2; l++) {
            int idx = tid + l * 256;            // 0..511 float4 slots
            int m = idx >> 2;                   // 0..127 row
            int kq = (idx & 3) * 4;             // 0,4,8,12
            float4 va = *(const float4*)(Ab + (size_t)m * K + k0 + kq);
            As[kq + 0][m] = va.x; As[kq + 1][m] = va.y;
            As[kq + 2][m] = va.z; As[kq + 3][m] = va.w;
            float4 vb = *(const float4*)(Bb + (size_t)m * K + k0 + kq);
            Bs[kq + 0][m] = vb.x; Bs[kq + 1][m] = vb.y;
            Bs[kq + 2][m] = vb.z; Bs[kq + 3][m] = vb.w;
        }
        __syncthreads();

#pragma unroll
        for (int kk = 0; kk < 16; kk++) {
            float ra[8], rb[8];
#pragma unroll
            for (int i = 0; i < 8; i++) ra[i] = As[kk][ty * 8 + i];
#pragma unroll
            for (int j = 0; j < 8; j++) rb[j] = Bs[kk][tx + 16 * j];
#pragma unroll
            for (int i = 0; i < 8; i++)
#pragma unroll
                for (int j = 0; j < 8; j++) acc[i][j] += ra[i] * rb[j];
        }
        __syncthreads();
    }

    const int rowb = blockIdx.y * 128;
    const int colb = blockIdx.x * 128;
#pragma unroll
    for (int i = 0; i < 8; i++) {
        int r = rowb + ty * 8 + i;
#pragma unroll
        for (int j = 0; j < 8; j++) {
            int c = colb + tx + 16 * j;
            float v = acc[i][j];
            if (bias) v += bias[c];
            C[(size_t)r * N + c] = v;
        }
    }
}

// ---------------------------------------------------------------------------
// Attention: one block per (b, h, 64-query tile). 256 threads.
// Online-softmax over 32-key KV tiles. Thread (ty,tx): rows ty*4+i (i<4),
// S columns tx+16j (j<2), O columns tx+16j (j<4).
// qkv layout: row m=(b*L+l), 1536 floats: [q(512) | k(512) | v(512)],
// per-head slice at h*64.
// ---------------------------------------------------------------------------
__global__ __launch_bounds__(256) void attn_kernel(
    const float* __restrict__ qkv, const int* __restrict__ amask,
    float* __restrict__ out)
{
    __shared__ float Qs[64][65];
    __shared__ float Ks[32][65];
    __shared__ float Vs[32][65];
    __shared__ float Ps[64][33];

    const int tid = threadIdx.x;
    const int tx = tid & 15;
    const int ty = tid >> 4;
    const int b = blockIdx.z;
    const int h = blockIdx.y;
    const int q0 = blockIdx.x * 64;
    const size_t rs = NQKV;

    // Load Q tile (64x64), 4 float4 per thread
    const float* qbase = qkv + (size_t)(b * NL + q0) * rs + h * NHD;
#pragma unroll
    for (int l = 0; l < 4; l++) {
        int f = tid + l * 256;
        int r = f >> 4;
        int dq = (f & 15) * 4;
        float4 v = *(const float4*)(qbase + (size_t)r * rs + dq);
        Qs[r][dq] = v.x; Qs[r][dq + 1] = v.y;
        Qs[r][dq + 2] = v.z; Qs[r][dq + 3] = v.w;
    }

    float o[4][4];
    float mrow[4], lrow[4];
#pragma unroll
    for (int i = 0; i < 4; i++) {
        mrow[i] = -1e30f;
        lrow[i] = 0.0f;
#pragma unroll
        for (int j = 0; j < 4; j++) o[i][j] = 0.0f;
    }
    const float scale = 0.125f;  // 1/sqrt(64)

    for (int jt = 0; jt < NL / 32; jt++) {
        __syncthreads();  // previous O-update done (and Q loaded) before overwrite
        const float* kbase = qkv + (size_t)(b * NL + jt * 32) * rs + ND + h * NHD;
        const float* vbase = kbase + ND;
#pragma unroll
        for (int l = 0; l < 2; l++) {
            int f = tid + l * 256;
            int r = f >> 4;
            int dq = (f & 15) * 4;
            float4 kv = *(const float4*)(kbase + (size_t)r * rs + dq);
            Ks[r][dq] = kv.x; Ks[r][dq + 1] = kv.y;
            Ks[r][dq + 2] = kv.z; Ks[r][dq + 3] = kv.w;
            float4 vv = *(const float4*)(vbase + (size_t)r * rs + dq);
            Vs[r][dq] = vv.x; Vs[r][dq + 1] = vv.y;
            Vs[r][dq + 2] = vv.z; Vs[r][dq + 3] = vv.w;
        }
        __syncthreads();

        // S = Q K^T (4 rows x 2 cols per thread)
        float s[4][2];
#pragma unroll
        for (int i = 0; i < 4; i++) { s[i][0] = 0.0f; s[i][1] = 0.0f; }
#pragma unroll 16
        for (int d = 0; d < 64; d++) {
            float rq[4], rk[2];
#pragma unroll
            for (int i = 0; i < 4; i++) rq[i] = Qs[ty * 4 + i][d];
            rk[0] = Ks[tx][d];
            rk[1] = Ks[tx + 16][d];
#pragma unroll
            for (int i = 0; i < 4; i++) {
                s[i][0] += rq[i] * rk[0];
                s[i][1] += rq[i] * rk[1];
            }
        }

        // scale + clamp + padding mask (combined-mask of reference is provably
        // always > 0 since softmax weights are strictly positive -> no-op)
        const int mv0 = amask[b * NL + jt * 32 + tx];
        const int mv1 = amask[b * NL + jt * 32 + tx + 16];
#pragma unroll
        for (int i = 0; i < 4; i++) {
#pragma unroll
            for (int j = 0; j < 2; j++) {
                float v = s[i][j] * scale;
                v = fminf(fmaxf(v, NEGV), -NEGV);
                if ((j ? mv1 : mv0) == 0) v = NEGV;
                s[i][j] = v;
            }
        }

        // row max across 2 local cols + 16-lane group (lanes with same ty)
        float rmax[4];
#pragma unroll
        for (int i = 0; i < 4; i++) {
            float v = fmaxf(s[i][0], s[i][1]);
#pragma unroll
            for (int m = 1; m < 16; m <<= 1)
                v = fmaxf(v, __shfl_xor_sync(0xffffffffu, v, m));
            rmax[i] = v;
        }

        float alpha[4];
#pragma unroll
        for (int i = 0; i < 4; i++) {
            float mn = fmaxf(mrow[i], rmax[i]);
            alpha[i] = __expf(mrow[i] - mn);
            mrow[i] = mn;
        }

        float psum[4];
#pragma unroll
        for (int i = 0; i < 4; i++) {
            float p0 = __expf(s[i][0] - mrow[i]);
            float p1 = __expf(s[i][1] - mrow[i]);
            Ps[ty * 4 + i][tx] = p0;
            Ps[ty * 4 + i][tx + 16] = p1;
            float v = p0 + p1;
#pragma unroll
            for (int m = 1; m < 16; m <<= 1)
                v += __shfl_xor_sync(0xffffffffu, v, m);
            psum[i] = v;
        }
#pragma unroll
        for (int i = 0; i < 4; i++) {
            lrow[i] = lrow[i] * alpha[i] + psum[i];
#pragma unroll
            for (int j = 0; j < 4; j++) o[i][j] *= alpha[i];
        }
        __syncthreads();  // Ps visible to all

        // O += P V  (4 rows x 4 d-cols per thread)
#pragma unroll 8
        for (int jj = 0; jj < 32; jj++) {
            float rv[4], rp[4];
#pragma unroll
            for (int j = 0; j < 4; j++) rv[j] = Vs[jj][tx + 16 * j];
#pragma unroll
            for (int i = 0; i < 4; i++) rp[i] = Ps[ty * 4 + i][jj];
#pragma unroll
            for (int i = 0; i < 4; i++)
#pragma unroll
                for (int j = 0; j < 4; j++) o[i][j] += rp[i] * rv[j];
        }
    }

    // epilogue: normalize and store to (b, l, h*64+d) layout
#pragma unroll
    for (int i = 0; i < 4; i++) {
        float inv = 1.0f / lrow[i];
        size_t rowoff = (size_t)(b * NL + q0 + ty * 4 + i) * ND + h * NHD;
#pragma unroll
        for (int j = 0; j < 4; j++)
            out[rowoff + tx + 16 * j] = o[i][j] * inv;
    }
}

// ---------------------------------------------------------------------------
extern "C" void kernel_launch(void* const* d_in, const int* in_sizes, int n_in,
                              void* d_out, int out_size)
{
    const float* x      = (const float*)d_in[0];
    const int*   amask  = (const int*)d_in[1];
    const float* qkv_w  = (const float*)d_in[2];
    const float* proj_w = (const float*)d_in[3];
    const float* proj_b = (const float*)d_in[4];
    // d_in[5..10]: selector / sparse params — provably dead code (see analysis)
    float* out = (float*)d_out;

    void* qkv_ptr = nullptr;
    void* attn_ptr = nullptr;
    cudaGetSymbolAddress(&qkv_ptr, g_qkv);
    cudaGetSymbolAddress(&attn_ptr, g_attn);
    float* qkvb = (float*)qkv_ptr;
    float* attnb = (float*)attn_ptr;

    // 1) QKV projection: (4096 x 512) @ (1536 x 512)^T -> 4096 x 1536
    sgemm_tn_kernel<<<dim3(NQKV / 128, NM / 128), 256>>>(
        x, qkv_w, nullptr, qkvb, NM, NQKV, ND);

    // 2) attention
    attn_kernel<<<dim3(NL / 64, NH, NB), 256>>>(qkvb, amask, attnb);

    // 3) output projection: (4096 x 512) @ (512 x 512)^T + bias
    sgemm_tn_kernel<<<dim3(ND / 128, NM / 128), 256>>>(
        attnb, proj_w, proj_b, out, NM, ND, ND);
}